// round 10
// baseline (speedup 1.0000x reference)
#include <cuda_runtime.h>
#include <cuda_fp16.h>

// inputs [B=2,T=16,V=10000,F=32] f32; L_vals[160000] f32; L_rows sorted i32; L_cols i32
// out[bt,i,f] = sum_{e: rows[e]==i} vals[e] * x[bt,cols[e],f]
//
// Pipeline:
//  1) prep_kernel (fused): convert x to PAIRED fp16 (one 128B line per (pair,
//     vertex) = [slice 2p | slice 2p+1]) + boundary-scatter CSR row_ptr.
//  2) spmm_h_kernel: warp per (vertex, 4-pair group = 8 slices). Per edge:
//     2x LDG.64 (each spans 2 lines -> cheaper L1 replay than 1x LDG.128).
//     Edges zero-padded to 4-granularity: no scalar tail, constant 8-deep MLP.

#define BT    32
#define NV    10000
#define NF    32
#define NNZ_  160000
#define NPAIR 16
#define PG    4               // pair-groups of 4 pairs (8 slices) per warp

#define WARPS_CTA 4

#define CONV_THREADS (NPAIR * NV * 8)        // one 16B chunk each
#define CONV_BLOCKS  (CONV_THREADS / 256)    // 5000
#define SCAT_BLOCKS  ((NNZ_ + 255) / 256)    // 625

__device__ int g_row_ptr[NV + 1];
// fp16 paired x: [NPAIR][NV] lines of 128B = 20.48 MB (L2-resident).
__device__ uint4 g_xh4[(size_t)NPAIR * NV * 8];

__global__ void __launch_bounds__(256) prep_kernel(
    const float* __restrict__ x, const int* __restrict__ rows)
{
    if (blockIdx.x < CONV_BLOCKS) {
        // ---- convert: thread -> (p, v, s, q); 32B read, 16B write ----
        int gtid = blockIdx.x * 256 + threadIdx.x;
        int p    = gtid / (NV * 8);
        int rem  = gtid - p * (NV * 8);
        int v    = rem >> 3;
        int s    = (rem >> 2) & 1;   // slice within pair
        int q    = rem & 3;          // 16B chunk within the 64B slice-half

        const float4* src =
            (const float4*)(x + ((size_t)(2 * p + s) * NV + v) * NF + q * 8);
        float4 a = __ldg(src);
        float4 b = __ldg(src + 1);

        __half2 h0 = __floats2half2_rn(a.x, a.y);
        __half2 h1 = __floats2half2_rn(a.z, a.w);
        __half2 h2 = __floats2half2_rn(b.x, b.y);
        __half2 h3 = __floats2half2_rn(b.z, b.w);
        uint4 pk;
        pk.x = *(const unsigned*)&h0;
        pk.y = *(const unsigned*)&h1;
        pk.z = *(const unsigned*)&h2;
        pk.w = *(const unsigned*)&h3;

        g_xh4[((size_t)p * NV + v) * 8 + s * 4 + q] = pk;
    } else {
        // ---- CSR row_ptr boundary scatter (rows sorted ascending) ----
        int e = (blockIdx.x - CONV_BLOCKS) * 256 + threadIdx.x;
        if (e >= NNZ_) return;
        int r  = __ldg(rows + e);
        int rp = (e == 0) ? -1 : __ldg(rows + e - 1);
        for (int v = rp + 1; v <= r; ++v) g_row_ptr[v] = e;
        if (e == NNZ_ - 1)
            for (int v = r + 1; v <= NV; ++v) g_row_ptr[v] = NNZ_;
    }
}

// uint2 = 8B = 4 halves: accumulate into acc[4] (fp32).
__device__ __forceinline__ void fma4(float acc[4], uint2 g, float w) {
    float2 f;
    f = __half22float2(*(__half2*)&g.x);
    acc[0] = fmaf(w, f.x, acc[0]); acc[1] = fmaf(w, f.y, acc[1]);
    f = __half22float2(*(__half2*)&g.y);
    acc[2] = fmaf(w, f.x, acc[2]); acc[3] = fmaf(w, f.y, acc[3]);
}

// Warp = (vertex v, pair-group pg of 4 pairs = 8 slices).
// pq = lane>>4 (pair within LDG set), d = lane&15 (8B chunk of the 128B line).
// LDG A covers pairs pg*4+{0,1}; LDG B covers pairs pg*4+{2,3}.
// Lane's 4 halves = features (d&7)*4.. of slice 2p+(d>>3).
__global__ void __launch_bounds__(WARPS_CTA * 32) spmm_h_kernel(
    const float* __restrict__ vals,   // [NNZ]
    const int*   __restrict__ cols,   // [NNZ]
    float*       __restrict__ out)    // [BT, V, F]
{
    const int warp = threadIdx.x >> 5;
    const int lane = threadIdx.x & 31;
    const int v    = blockIdx.x * WARPS_CTA + warp;   // grid.x*4 == NV exactly
    const int pg   = blockIdx.y;

    const int pq = lane >> 4;
    const int d  = lane & 15;
    const int pA = pg * 4 + pq;
    const int pB = pg * 4 + 2 + pq;
    const int hs = d >> 3;            // slice within pair
    const int f0 = (d & 7) * 4;       // 4 consecutive features

    const uint2* __restrict__ xg = (const uint2*)g_xh4;
    const uint2* __restrict__ xpA = xg + ((size_t)pA * NV) * 16 + d;
    const uint2* __restrict__ xpB = xg + ((size_t)pB * NV) * 16 + d;

    const int s = g_row_ptr[v];
    const int e = g_row_ptr[v + 1];

    float accA[4] = {0.f, 0.f, 0.f, 0.f};
    float accB[4] = {0.f, 0.f, 0.f, 0.f};

    for (int base = s; base < e; base += 32) {
        int n = e - base;                      // uniform across warp
        if (n > 32) n = 32;
        int m = (n + 3) & ~3;                  // pad to 4-edge granularity
        int idx = min(base + lane, NNZ_ - 1);  // clamp: valid col for pad lanes
        int   cc = __ldg(cols + idx);
        float ww = (lane < n) ? __ldg(vals + idx) : 0.f;  // pad weight = 0

        #pragma unroll 1
        for (int j = 0; j < m; j += 4) {
            int   c0 = __shfl_sync(0xffffffffu, cc, j);
            int   c1 = __shfl_sync(0xffffffffu, cc, j + 1);
            int   c2 = __shfl_sync(0xffffffffu, cc, j + 2);
            int   c3 = __shfl_sync(0xffffffffu, cc, j + 3);
            float w0 = __shfl_sync(0xffffffffu, ww, j);
            float w1 = __shfl_sync(0xffffffffu, ww, j + 1);
            float w2 = __shfl_sync(0xffffffffu, ww, j + 2);
            float w3 = __shfl_sync(0xffffffffu, ww, j + 3);
            uint2 a0 = __ldg(xpA + (size_t)c0 * 16);
            uint2 b0 = __ldg(xpB + (size_t)c0 * 16);
            uint2 a1 = __ldg(xpA + (size_t)c1 * 16);
            uint2 b1 = __ldg(xpB + (size_t)c1 * 16);
            uint2 a2 = __ldg(xpA + (size_t)c2 * 16);
            uint2 b2 = __ldg(xpB + (size_t)c2 * 16);
            uint2 a3 = __ldg(xpA + (size_t)c3 * 16);
            uint2 b3 = __ldg(xpB + (size_t)c3 * 16);
            fma4(accA, a0, w0); fma4(accB, b0, w0);
            fma4(accA, a1, w1); fma4(accB, b1, w1);
            fma4(accA, a2, w2); fma4(accB, b2, w2);
            fma4(accA, a3, w3); fma4(accB, b3, w3);
        }
    }

    const int btA = 2 * pA + hs;
    const int btB = 2 * pB + hs;
    float* oA = out + ((size_t)btA * NV + v) * NF + f0;
    float* oB = out + ((size_t)btB * NV + v) * NF + f0;
    *(float4*)oA = make_float4(accA[0], accA[1], accA[2], accA[3]);
    *(float4*)oB = make_float4(accB[0], accB[1], accB[2], accB[3]);
}

extern "C" void kernel_launch(void* const* d_in, const int* in_sizes, int n_in,
                              void* d_out, int out_size) {
    const float* x    = (const float*)d_in[0];
    const float* vals = (const float*)d_in[1];
    const int*   rows = (const int*)  d_in[2];
    const int*   cols = (const int*)  d_in[3];
    float*       out  = (float*)d_out;

    (void)in_sizes; (void)n_in; (void)out_size;

    // Fused convert + row_ptr scatter (independent work, block-partitioned).
    prep_kernel<<<CONV_BLOCKS + SCAT_BLOCKS, 256>>>(x, rows);

    // SpMM: warp per (v, pair-group). grid = (NV/4, 4).
    dim3 grid(NV / WARPS_CTA, PG);
    spmm_h_kernel<<<grid, WARPS_CTA * 32>>>(vals, cols, out);
}

// round 12
// speedup vs baseline: 1.0462x; 1.0462x over previous
#include <cuda_runtime.h>
#include <cuda_fp16.h>

// inputs [B=2,T=16,V=10000,F=32] f32; L_vals[160000] f32; L_rows sorted i32; L_cols i32
// out[bt,i,f] = sum_{e: rows[e]==i} vals[e] * x[bt,cols[e],f]
//
// Pipeline:
//  1) prep_kernel (fused): convert x to PAIRED fp16 (one 128B line per (pair,
//     vertex) = [slice 2p | slice 2p+1]) + boundary-scatter CSR row_ptr.
//  2) spmm_h_kernel: warp per (vertex, 4-pair group = 8 slices). One LDG.128
//     per edge gathers 8 slices (4 lines). 8 edges in flight (8 LDG.128),
//     edge batches zero-padded to 8 -> no scalar tail. fp32 accumulate.

#define BT    32
#define NV    10000
#define NF    32
#define NNZ_  160000
#define NPAIR 16
#define PG    4               // pair-groups of 4 pairs (8 slices) per warp

#define WARPS_CTA 4

#define CONV_THREADS (NPAIR * NV * 8)        // one 16B chunk each
#define CONV_BLOCKS  (CONV_THREADS / 256)    // 5000
#define SCAT_BLOCKS  ((NNZ_ + 255) / 256)    // 625

__device__ int g_row_ptr[NV + 1];
// fp16 paired x: [NPAIR][NV] lines of 128B = 20.48 MB (L2-resident).
__device__ uint4 g_xh4[(size_t)NPAIR * NV * 8];

__global__ void __launch_bounds__(256) prep_kernel(
    const float* __restrict__ x, const int* __restrict__ rows)
{
    if (blockIdx.x < CONV_BLOCKS) {
        // ---- convert: thread -> (p, v, s, q); 32B read, 16B write ----
        int gtid = blockIdx.x * 256 + threadIdx.x;
        int p    = gtid / (NV * 8);
        int rem  = gtid - p * (NV * 8);
        int v    = rem >> 3;
        int s    = (rem >> 2) & 1;   // slice within pair
        int q    = rem & 3;          // 16B chunk within the 64B slice-half

        const float4* src =
            (const float4*)(x + ((size_t)(2 * p + s) * NV + v) * NF + q * 8);
        float4 a = __ldg(src);
        float4 b = __ldg(src + 1);

        __half2 h0 = __floats2half2_rn(a.x, a.y);
        __half2 h1 = __floats2half2_rn(a.z, a.w);
        __half2 h2 = __floats2half2_rn(b.x, b.y);
        __half2 h3 = __floats2half2_rn(b.z, b.w);
        uint4 pk;
        pk.x = *(const unsigned*)&h0;
        pk.y = *(const unsigned*)&h1;
        pk.z = *(const unsigned*)&h2;
        pk.w = *(const unsigned*)&h3;

        g_xh4[((size_t)p * NV + v) * 8 + s * 4 + q] = pk;
    } else {
        // ---- CSR row_ptr boundary scatter (rows sorted ascending) ----
        int e = (blockIdx.x - CONV_BLOCKS) * 256 + threadIdx.x;
        if (e >= NNZ_) return;
        int r  = __ldg(rows + e);
        int rp = (e == 0) ? -1 : __ldg(rows + e - 1);
        for (int v = rp + 1; v <= r; ++v) g_row_ptr[v] = e;
        if (e == NNZ_ - 1)
            for (int v = r + 1; v <= NV; ++v) g_row_ptr[v] = NNZ_;
    }
}

__device__ __forceinline__ void fma8(float acc[8], uint4 g, float w) {
    __half2 h; float2 f;
    h = *(__half2*)&g.x; f = __half22float2(h);
    acc[0] = fmaf(w, f.x, acc[0]); acc[1] = fmaf(w, f.y, acc[1]);
    h = *(__half2*)&g.y; f = __half22float2(h);
    acc[2] = fmaf(w, f.x, acc[2]); acc[3] = fmaf(w, f.y, acc[3]);
    h = *(__half2*)&g.z; f = __half22float2(h);
    acc[4] = fmaf(w, f.x, acc[4]); acc[5] = fmaf(w, f.y, acc[5]);
    h = *(__half2*)&g.w; f = __half22float2(h);
    acc[6] = fmaf(w, f.x, acc[6]); acc[7] = fmaf(w, f.y, acc[7]);
}

// One warp per (vertex v, pair-group pg of 4 pairs = 8 slices).
// Lane = pp*8 + c: pp = pair-in-group, c = 16B chunk of the 128B line.
// One LDG.128 per edge gathers 8 slices' feature rows (4 lines).
// 8 edges in flight; batches padded to 8 with zero weights (no scalar tail).
__global__ void __launch_bounds__(WARPS_CTA * 32) spmm_h_kernel(
    const float* __restrict__ vals,   // [NNZ]
    const int*   __restrict__ cols,   // [NNZ]
    float*       __restrict__ out)    // [BT, V, F]
{
    const int warp = threadIdx.x >> 5;
    const int lane = threadIdx.x & 31;
    const int v    = blockIdx.x * WARPS_CTA + warp;   // grid.x*4 == NV exactly
    const int pg   = blockIdx.y;

    const int pp = lane >> 3;
    const int c  = lane & 7;
    const int p  = pg * 4 + pp;
    const int bt = 2 * p + (c >> 2);
    const int f0 = (c & 3) * 8;

    const uint4* __restrict__ xp = g_xh4 + (size_t)p * NV * 8 + c;

    const int s = g_row_ptr[v];
    const int e = g_row_ptr[v + 1];

    float acc[8] = {0.f, 0.f, 0.f, 0.f, 0.f, 0.f, 0.f, 0.f};

    for (int base = s; base < e; base += 32) {
        int n = e - base;                      // uniform across warp
        if (n > 32) n = 32;
        int m = (n + 7) & ~7;                  // pad to 8-edge granularity
        int idx = min(base + lane, NNZ_ - 1);  // clamp: valid col for pad lanes
        int   cc = __ldg(cols + idx);
        float wl = __ldg(vals + idx);
        float ww = (lane < n) ? wl : 0.f;      // pad weight = 0

        #pragma unroll 1
        for (int j = 0; j < m; j += 8) {
            int c0 = __shfl_sync(0xffffffffu, cc, j);
            int c1 = __shfl_sync(0xffffffffu, cc, j + 1);
            int c2 = __shfl_sync(0xffffffffu, cc, j + 2);
            int c3 = __shfl_sync(0xffffffffu, cc, j + 3);
            int c4 = __shfl_sync(0xffffffffu, cc, j + 4);
            int c5 = __shfl_sync(0xffffffffu, cc, j + 5);
            int c6 = __shfl_sync(0xffffffffu, cc, j + 6);
            int c7 = __shfl_sync(0xffffffffu, cc, j + 7);
            float w0 = __shfl_sync(0xffffffffu, ww, j);
            float w1 = __shfl_sync(0xffffffffu, ww, j + 1);
            float w2 = __shfl_sync(0xffffffffu, ww, j + 2);
            float w3 = __shfl_sync(0xffffffffu, ww, j + 3);
            float w4 = __shfl_sync(0xffffffffu, ww, j + 4);
            float w5 = __shfl_sync(0xffffffffu, ww, j + 5);
            float w6 = __shfl_sync(0xffffffffu, ww, j + 6);
            float w7 = __shfl_sync(0xffffffffu, ww, j + 7);
            uint4 g0 = __ldg(xp + (size_t)c0 * 8);
            uint4 g1 = __ldg(xp + (size_t)c1 * 8);
            uint4 g2 = __ldg(xp + (size_t)c2 * 8);
            uint4 g3 = __ldg(xp + (size_t)c3 * 8);
            uint4 g4 = __ldg(xp + (size_t)c4 * 8);
            uint4 g5 = __ldg(xp + (size_t)c5 * 8);
            uint4 g6 = __ldg(xp + (size_t)c6 * 8);
            uint4 g7 = __ldg(xp + (size_t)c7 * 8);
            fma8(acc, g0, w0);
            fma8(acc, g1, w1);
            fma8(acc, g2, w2);
            fma8(acc, g3, w3);
            fma8(acc, g4, w4);
            fma8(acc, g5, w5);
            fma8(acc, g6, w6);
            fma8(acc, g7, w7);
        }
    }

    float* o = out + ((size_t)bt * NV + v) * NF + f0;
    *(float4*)(o)     = make_float4(acc[0], acc[1], acc[2], acc[3]);
    *(float4*)(o + 4) = make_float4(acc[4], acc[5], acc[6], acc[7]);
}

extern "C" void kernel_launch(void* const* d_in, const int* in_sizes, int n_in,
                              void* d_out, int out_size) {
    const float* x    = (const float*)d_in[0];
    const float* vals = (const float*)d_in[1];
    const int*   rows = (const int*)  d_in[2];
    const int*   cols = (const int*)  d_in[3];
    float*       out  = (float*)d_out;

    (void)in_sizes; (void)n_in; (void)out_size;

    // Fused convert + row_ptr scatter (independent work, block-partitioned).
    prep_kernel<<<CONV_BLOCKS + SCAT_BLOCKS, 256>>>(x, rows);

    // SpMM: warp per (v, pair-group). grid = (NV/4, 4).
    dim3 grid(NV / WARPS_CTA, PG);
    spmm_h_kernel<<<grid, WARPS_CTA * 32>>>(vals, cols, out);
}

// round 13
// speedup vs baseline: 1.1410x; 1.0906x over previous
#include <cuda_runtime.h>
#include <cuda_fp16.h>

// inputs [B=2,T=16,V=10000,F=32] f32; L_vals[160000] f32; L_rows sorted i32; L_cols i32
// out[bt,i,f] = sum_{e: rows[e]==i} vals[e] * x[bt,cols[e],f]
//
// Pipeline:
//  1) prep_kernel (fused): convert x to PAIRED fp16 (one 128B line per (pair,
//     vertex) = [slice 2p | slice 2p+1]) + boundary-scatter CSR row_ptr.
//  2) spmm_h_kernel: warp per (vertex, 4-pair group = 8 slices). One LDG.128
//     per edge gathers 8 slices (4 lines). 4 edges in flight, scalar tail
//     (r8 structure — best measured). Math in packed HFMA2 with even/odd
//     half2 accumulator sets; f32 epilogue.

#define BT    32
#define NV    10000
#define NF    32
#define NNZ_  160000
#define NPAIR 16
#define PG    4               // pair-groups of 4 pairs (8 slices) per warp

#define WARPS_CTA 4

#define CONV_THREADS (NPAIR * NV * 8)        // one 16B chunk each
#define CONV_BLOCKS  (CONV_THREADS / 256)    // 5000
#define SCAT_BLOCKS  ((NNZ_ + 255) / 256)    // 625

__device__ int g_row_ptr[NV + 1];
// fp16 paired x: [NPAIR][NV] lines of 128B = 20.48 MB (L2-resident).
__device__ uint4 g_xh4[(size_t)NPAIR * NV * 8];

__global__ void __launch_bounds__(256) prep_kernel(
    const float* __restrict__ x, const int* __restrict__ rows)
{
    if (blockIdx.x < CONV_BLOCKS) {
        // ---- convert: thread -> (p, v, s, q); 32B read, 16B write ----
        int gtid = blockIdx.x * 256 + threadIdx.x;
        int p    = gtid / (NV * 8);
        int rem  = gtid - p * (NV * 8);
        int v    = rem >> 3;
        int s    = (rem >> 2) & 1;   // slice within pair
        int q    = rem & 3;          // 16B chunk within the 64B slice-half

        const float4* src =
            (const float4*)(x + ((size_t)(2 * p + s) * NV + v) * NF + q * 8);
        float4 a = __ldg(src);
        float4 b = __ldg(src + 1);

        __half2 h0 = __floats2half2_rn(a.x, a.y);
        __half2 h1 = __floats2half2_rn(a.z, a.w);
        __half2 h2 = __floats2half2_rn(b.x, b.y);
        __half2 h3 = __floats2half2_rn(b.z, b.w);
        uint4 pk;
        pk.x = *(const unsigned*)&h0;
        pk.y = *(const unsigned*)&h1;
        pk.z = *(const unsigned*)&h2;
        pk.w = *(const unsigned*)&h3;

        g_xh4[((size_t)p * NV + v) * 8 + s * 4 + q] = pk;
    } else {
        // ---- CSR row_ptr boundary scatter (rows sorted ascending) ----
        int e = (blockIdx.x - CONV_BLOCKS) * 256 + threadIdx.x;
        if (e >= NNZ_) return;
        int r  = __ldg(rows + e);
        int rp = (e == 0) ? -1 : __ldg(rows + e - 1);
        for (int v = rp + 1; v <= r; ++v) g_row_ptr[v] = e;
        if (e == NNZ_ - 1)
            for (int v = r + 1; v <= NV; ++v) g_row_ptr[v] = NNZ_;
    }
}

__device__ __forceinline__ __half2 u2h(unsigned u) { return *(__half2*)&u; }

// 4 HFMA2: g (uint4 = 8 halves) * wh into 4 half2 accumulators.
__device__ __forceinline__ void hfma4x2(__half2 acc[4], uint4 g, __half2 wh) {
    acc[0] = __hfma2(u2h(g.x), wh, acc[0]);
    acc[1] = __hfma2(u2h(g.y), wh, acc[1]);
    acc[2] = __hfma2(u2h(g.z), wh, acc[2]);
    acc[3] = __hfma2(u2h(g.w), wh, acc[3]);
}

// One warp per (vertex v, pair-group pg of 4 pairs = 8 slices).
// Lane = pp*8 + c: pp = pair-in-group, c = 16B chunk of the 128B line.
// One LDG.128 per edge gathers 8 slices' feature rows (4 lines).
// Even/odd edges go to separate half2 accumulator sets (limits fp16 chain
// length to ~deg/2); f32 combine at the end.
__global__ void __launch_bounds__(WARPS_CTA * 32) spmm_h_kernel(
    const float* __restrict__ vals,   // [NNZ]
    const int*   __restrict__ cols,   // [NNZ]
    float*       __restrict__ out)    // [BT, V, F]
{
    const int warp = threadIdx.x >> 5;
    const int lane = threadIdx.x & 31;
    const int v    = blockIdx.x * WARPS_CTA + warp;   // grid.x*4 == NV exactly
    const int pg   = blockIdx.y;

    const int pp = lane >> 3;
    const int c  = lane & 7;
    const int p  = pg * 4 + pp;
    const int bt = 2 * p + (c >> 2);
    const int f0 = (c & 3) * 8;

    const uint4* __restrict__ xp = g_xh4 + (size_t)p * NV * 8 + c;

    const int s = g_row_ptr[v];
    const int e = g_row_ptr[v + 1];

    __half2 ze = __floats2half2_rn(0.f, 0.f);
    __half2 accE[4] = {ze, ze, ze, ze};
    __half2 accO[4] = {ze, ze, ze, ze};

    for (int base = s; base < e; base += 32) {
        int n = e - base;                      // uniform across warp
        if (n > 32) n = 32;
        int idx = min(base + lane, NNZ_ - 1);  // clamp: valid col always
        int cc = __ldg(cols + idx);
        float wf = (lane < n) ? __ldg(vals + idx) : 0.f;
        __half2 whh = __floats2half2_rn(wf, wf);
        unsigned wu = *(unsigned*)&whh;        // shuffle as u32

        int j = 0;
        #pragma unroll 1
        for (; j + 3 < n; j += 4) {
            int      c0 = __shfl_sync(0xffffffffu, cc, j);
            int      c1 = __shfl_sync(0xffffffffu, cc, j + 1);
            int      c2 = __shfl_sync(0xffffffffu, cc, j + 2);
            int      c3 = __shfl_sync(0xffffffffu, cc, j + 3);
            unsigned u0 = __shfl_sync(0xffffffffu, wu, j);
            unsigned u1 = __shfl_sync(0xffffffffu, wu, j + 1);
            unsigned u2 = __shfl_sync(0xffffffffu, wu, j + 2);
            unsigned u3 = __shfl_sync(0xffffffffu, wu, j + 3);
            uint4 g0 = __ldg(xp + (size_t)c0 * 8);
            uint4 g1 = __ldg(xp + (size_t)c1 * 8);
            uint4 g2 = __ldg(xp + (size_t)c2 * 8);
            uint4 g3 = __ldg(xp + (size_t)c3 * 8);
            hfma4x2(accE, g0, u2h(u0));
            hfma4x2(accO, g1, u2h(u1));
            hfma4x2(accE, g2, u2h(u2));
            hfma4x2(accO, g3, u2h(u3));
        }
        #pragma unroll 1
        for (; j < n; ++j) {
            int      c0 = __shfl_sync(0xffffffffu, cc, j);
            unsigned u0 = __shfl_sync(0xffffffffu, wu, j);
            uint4 g0 = __ldg(xp + (size_t)c0 * 8);
            if (j & 1) hfma4x2(accO, g0, u2h(u0));
            else       hfma4x2(accE, g0, u2h(u0));
        }
    }

    // f32 epilogue: combine even/odd sets.
    float2 e0 = __half22float2(accE[0]), o0 = __half22float2(accO[0]);
    float2 e1 = __half22float2(accE[1]), o1 = __half22float2(accO[1]);
    float2 e2 = __half22float2(accE[2]), o2 = __half22float2(accO[2]);
    float2 e3 = __half22float2(accE[3]), o3 = __half22float2(accO[3]);

    float* o = out + ((size_t)bt * NV + v) * NF + f0;
    *(float4*)(o)     = make_float4(e0.x + o0.x, e0.y + o0.y,
                                    e1.x + o1.x, e1.y + o1.y);
    *(float4*)(o + 4) = make_float4(e2.x + o2.x, e2.y + o2.y,
                                    e3.x + o3.x, e3.y + o3.y);
}

extern "C" void kernel_launch(void* const* d_in, const int* in_sizes, int n_in,
                              void* d_out, int out_size) {
    const float* x    = (const float*)d_in[0];
    const float* vals = (const float*)d_in[1];
    const int*   rows = (const int*)  d_in[2];
    const int*   cols = (const int*)  d_in[3];
    float*       out  = (float*)d_out;

    (void)in_sizes; (void)n_in; (void)out_size;

    // Fused convert + row_ptr scatter (independent work, block-partitioned).
    prep_kernel<<<CONV_BLOCKS + SCAT_BLOCKS, 256>>>(x, rows);

    // SpMM: warp per (v, pair-group). grid = (NV/4, 4).
    dim3 grid(NV / WARPS_CTA, PG);
    spmm_h_kernel<<<grid, WARPS_CTA * 32>>>(vals, cols, out);
}

// round 15
// speedup vs baseline: 1.1499x; 1.0078x over previous
#include <cuda_runtime.h>
#include <cuda_fp16.h>

// inputs [B=2,T=16,V=10000,F=32] f32; L_vals[160000] f32; L_rows sorted i32; L_cols i32
// out[bt,i,f] = sum_{e: rows[e]==i} vals[e] * x[bt,cols[e],f]
//
// Pipeline:
//  1) prep_kernel (fused): convert x to PAIRED fp16 (one 128B line per (pair,
//     vertex) = [slice 2p | slice 2p+1]) + boundary-scatter CSR row_ptr.
//  2) spmm_h_kernel: warp per (vertex, 4-pair group = 8 slices). One LDG.128
//     per edge gathers 8 slices (4 lines). 8-deep then 4-deep then scalar
//     stages, NO padding. Math in packed HFMA2 (even/odd half2 accumulator
//     sets), f32 epilogue.

#define BT    32
#define NV    10000
#define NF    32
#define NNZ_  160000
#define NPAIR 16
#define PG    4               // pair-groups of 4 pairs (8 slices) per warp

#define WARPS_CTA 4

#define PREP_T       512
#define CONV_THREADS (NPAIR * NV * 8)          // one 16B chunk each
#define CONV_BLOCKS  (CONV_THREADS / PREP_T)   // 2500
#define SCAT_BLOCKS  ((NNZ_ + PREP_T - 1) / PREP_T)  // 313

__device__ int g_row_ptr[NV + 1];
// fp16 paired x: [NPAIR][NV] lines of 128B = 20.48 MB (L2-resident).
__device__ uint4 g_xh4[(size_t)NPAIR * NV * 8];

__global__ void __launch_bounds__(PREP_T) prep_kernel(
    const float* __restrict__ x, const int* __restrict__ rows)
{
    if (blockIdx.x < CONV_BLOCKS) {
        // ---- convert: thread -> (p, v, s, q); 32B read, 16B write ----
        int gtid = blockIdx.x * PREP_T + threadIdx.x;
        int p    = gtid / (NV * 8);
        int rem  = gtid - p * (NV * 8);
        int v    = rem >> 3;
        int s    = (rem >> 2) & 1;   // slice within pair
        int q    = rem & 3;          // 16B chunk within the 64B slice-half

        const float4* src =
            (const float4*)(x + ((size_t)(2 * p + s) * NV + v) * NF + q * 8);
        float4 a = __ldg(src);
        float4 b = __ldg(src + 1);

        __half2 h0 = __floats2half2_rn(a.x, a.y);
        __half2 h1 = __floats2half2_rn(a.z, a.w);
        __half2 h2 = __floats2half2_rn(b.x, b.y);
        __half2 h3 = __floats2half2_rn(b.z, b.w);
        uint4 pk;
        pk.x = *(const unsigned*)&h0;
        pk.y = *(const unsigned*)&h1;
        pk.z = *(const unsigned*)&h2;
        pk.w = *(const unsigned*)&h3;

        g_xh4[((size_t)p * NV + v) * 8 + s * 4 + q] = pk;
    } else {
        // ---- CSR row_ptr boundary scatter (rows sorted ascending) ----
        int e = (blockIdx.x - CONV_BLOCKS) * PREP_T + threadIdx.x;
        if (e >= NNZ_) return;
        int r  = __ldg(rows + e);
        int rp = (e == 0) ? -1 : __ldg(rows + e - 1);
        for (int v = rp + 1; v <= r; ++v) g_row_ptr[v] = e;
        if (e == NNZ_ - 1)
            for (int v = r + 1; v <= NV; ++v) g_row_ptr[v] = NNZ_;
    }
}

__device__ __forceinline__ __half2 u2h(unsigned u) { return *(__half2*)&u; }

// 4 HFMA2: g (uint4 = 8 halves) * wh into 4 half2 accumulators.
__device__ __forceinline__ void hfma4x2(__half2 acc[4], uint4 g, __half2 wh) {
    acc[0] = __hfma2(u2h(g.x), wh, acc[0]);
    acc[1] = __hfma2(u2h(g.y), wh, acc[1]);
    acc[2] = __hfma2(u2h(g.z), wh, acc[2]);
    acc[3] = __hfma2(u2h(g.w), wh, acc[3]);
}

// One warp per (vertex v, pair-group pg of 4 pairs = 8 slices).
// Lane = pp*8 + c: pp = pair-in-group, c = 16B chunk of the 128B line.
// One LDG.128 per edge gathers 8 slices' feature rows (4 lines).
__global__ void __launch_bounds__(WARPS_CTA * 32) spmm_h_kernel(
    const float* __restrict__ vals,   // [NNZ]
    const int*   __restrict__ cols,   // [NNZ]
    float*       __restrict__ out)    // [BT, V, F]
{
    const int warp = threadIdx.x >> 5;
    const int lane = threadIdx.x & 31;
    const int v    = blockIdx.x * WARPS_CTA + warp;   // grid.x*4 == NV exactly
    const int pg   = blockIdx.y;

    const int pp = lane >> 3;
    const int c  = lane & 7;
    const int p  = pg * 4 + pp;
    const int bt = 2 * p + (c >> 2);
    const int f0 = (c & 3) * 8;

    const uint4* __restrict__ xp = g_xh4 + (size_t)p * NV * 8 + c;

    const int s = g_row_ptr[v];
    const int e = g_row_ptr[v + 1];

    __half2 ze = __floats2half2_rn(0.f, 0.f);
    __half2 accE[4] = {ze, ze, ze, ze};
    __half2 accO[4] = {ze, ze, ze, ze};

    for (int base = s; base < e; base += 32) {
        int n = e - base;                      // uniform across warp
        if (n > 32) n = 32;
        int idx = min(base + lane, NNZ_ - 1);  // clamp: valid col always
        int cc = __ldg(cols + idx);
        float wf = (lane < n) ? __ldg(vals + idx) : 0.f;
        __half2 whh = __floats2half2_rn(wf, wf);
        unsigned wu = *(unsigned*)&whh;        // shuffle as u32

        int j = 0;
        // 8-deep stage (no padding): 8 LDG.128 in flight.
        #pragma unroll 1
        for (; j + 7 < n; j += 8) {
            int      c0 = __shfl_sync(0xffffffffu, cc, j);
            int      c1 = __shfl_sync(0xffffffffu, cc, j + 1);
            int      c2 = __shfl_sync(0xffffffffu, cc, j + 2);
            int      c3 = __shfl_sync(0xffffffffu, cc, j + 3);
            int      c4 = __shfl_sync(0xffffffffu, cc, j + 4);
            int      c5 = __shfl_sync(0xffffffffu, cc, j + 5);
            int      c6 = __shfl_sync(0xffffffffu, cc, j + 6);
            int      c7 = __shfl_sync(0xffffffffu, cc, j + 7);
            unsigned u0 = __shfl_sync(0xffffffffu, wu, j);
            unsigned u1 = __shfl_sync(0xffffffffu, wu, j + 1);
            unsigned u2 = __shfl_sync(0xffffffffu, wu, j + 2);
            unsigned u3 = __shfl_sync(0xffffffffu, wu, j + 3);
            unsigned u4 = __shfl_sync(0xffffffffu, wu, j + 4);
            unsigned u5 = __shfl_sync(0xffffffffu, wu, j + 5);
            unsigned u6 = __shfl_sync(0xffffffffu, wu, j + 6);
            unsigned u7 = __shfl_sync(0xffffffffu, wu, j + 7);
            uint4 g0 = __ldg(xp + (size_t)c0 * 8);
            uint4 g1 = __ldg(xp + (size_t)c1 * 8);
            uint4 g2 = __ldg(xp + (size_t)c2 * 8);
            uint4 g3 = __ldg(xp + (size_t)c3 * 8);
            uint4 g4 = __ldg(xp + (size_t)c4 * 8);
            uint4 g5 = __ldg(xp + (size_t)c5 * 8);
            uint4 g6 = __ldg(xp + (size_t)c6 * 8);
            uint4 g7 = __ldg(xp + (size_t)c7 * 8);
            hfma4x2(accE, g0, u2h(u0));
            hfma4x2(accO, g1, u2h(u1));
            hfma4x2(accE, g2, u2h(u2));
            hfma4x2(accO, g3, u2h(u3));
            hfma4x2(accE, g4, u2h(u4));
            hfma4x2(accO, g5, u2h(u5));
            hfma4x2(accE, g6, u2h(u6));
            hfma4x2(accO, g7, u2h(u7));
        }
        // 4-deep stage.
        #pragma unroll 1
        for (; j + 3 < n; j += 4) {
            int      c0 = __shfl_sync(0xffffffffu, cc, j);
            int      c1 = __shfl_sync(0xffffffffu, cc, j + 1);
            int      c2 = __shfl_sync(0xffffffffu, cc, j + 2);
            int      c3 = __shfl_sync(0xffffffffu, cc, j + 3);
            unsigned u0 = __shfl_sync(0xffffffffu, wu, j);
            unsigned u1 = __shfl_sync(0xffffffffu, wu, j + 1);
            unsigned u2 = __shfl_sync(0xffffffffu, wu, j + 2);
            unsigned u3 = __shfl_sync(0xffffffffu, wu, j + 3);
            uint4 g0 = __ldg(xp + (size_t)c0 * 8);
            uint4 g1 = __ldg(xp + (size_t)c1 * 8);
            uint4 g2 = __ldg(xp + (size_t)c2 * 8);
            uint4 g3 = __ldg(xp + (size_t)c3 * 8);
            hfma4x2(accE, g0, u2h(u0));
            hfma4x2(accO, g1, u2h(u1));
            hfma4x2(accE, g2, u2h(u2));
            hfma4x2(accO, g3, u2h(u3));
        }
        // Scalar tail (<=3 edges).
        #pragma unroll 1
        for (; j < n; ++j) {
            int      c0 = __shfl_sync(0xffffffffu, cc, j);
            unsigned u0 = __shfl_sync(0xffffffffu, wu, j);
            uint4 g0 = __ldg(xp + (size_t)c0 * 8);
            if (j & 1) hfma4x2(accO, g0, u2h(u0));
            else       hfma4x2(accE, g0, u2h(u0));
        }
    }

    // f32 epilogue: combine even/odd sets.
    float2 e0 = __half22float2(accE[0]), o0 = __half22float2(accO[0]);
    float2 e1 = __half22float2(accE[1]), o1 = __half22float2(accO[1]);
    float2 e2 = __half22float2(accE[2]), o2 = __half22float2(accO[2]);
    float2 e3 = __half22float2(accE[3]), o3 = __half22float2(accO[3]);

    float* o = out + ((size_t)bt * NV + v) * NF + f0;
    *(float4*)(o)     = make_float4(e0.x + o0.x, e0.y + o0.y,
                                    e1.x + o1.x, e1.y + o1.y);
    *(float4*)(o + 4) = make_float4(e2.x + o2.x, e2.y + o2.y,
                                    e3.x + o3.x, e3.y + o3.y);
}

extern "C" void kernel_launch(void* const* d_in, const int* in_sizes, int n_in,
                              void* d_out, int out_size) {
    const float* x    = (const float*)d_in[0];
    const float* vals = (const float*)d_in[1];
    const int*   rows = (const int*)  d_in[2];
    const int*   cols = (const int*)  d_in[3];
    float*       out  = (float*)d_out;

    (void)in_sizes; (void)n_in; (void)out_size;

    // Fused convert + row_ptr scatter (independent work, block-partitioned).
    prep_kernel<<<CONV_BLOCKS + SCAT_BLOCKS, PREP_T>>>(x, rows);

    // SpMM: warp per (v, pair-group). grid = (NV/4, 4).
    dim3 grid(NV / WARPS_CTA, PG);
    spmm_h_kernel<<<grid, WARPS_CTA * 32>>>(vals, cols, out);
}